// round 3
// baseline (speedup 1.0000x reference)
#include <cuda_runtime.h>

#define NROW 8192
#define DDIM 128
#define BM 128
#define BN 64
#define TM 8
#define TN 4
#define NCHUNK 32
#define INV_T 10.0f

// Scratch (device globals: no allocations allowed)
__device__ float g_eN[NROW * DDIM];   // normalized embeddings
__device__ int   g_lab[NROW];         // labels as int32
__device__ float g_sumexp[NROW];
__device__ float g_possum[NROW];
__device__ float g_npos[NROW];

// ---------------------------------------------------------------------------
// Kernel 0: label conversion with dtype sniffing (int32 vs int64).
// Labels are in [0, 100). If the buffer is int64, every odd 32-bit word (the
// high word) is 0. If int32, odd words are labels[1],[3],... (OR != 0 with
// certainty for this data). Scanning only the first NROW/2 odd words stays
// in-bounds for BOTH layouts. Single block so detection+convert can sync.
// ---------------------------------------------------------------------------
__global__ void labels_kernel(const int* __restrict__ raw) {
    __shared__ int s_or;
    if (threadIdx.x == 0) s_or = 0;
    __syncthreads();
    int local = 0;
    for (int i = threadIdx.x; i < NROW / 2; i += blockDim.x)
        local |= raw[2 * i + 1];
    if (local) atomicOr(&s_or, 1);
    __syncthreads();
    const bool is32 = (s_or != 0);
    for (int i = threadIdx.x; i < NROW; i += blockDim.x)
        g_lab[i] = is32 ? raw[i] : raw[2 * i];
}

// ---------------------------------------------------------------------------
// Kernel 1: L2-normalize rows (one warp per row), zero accumulators
// ---------------------------------------------------------------------------
__global__ void prep_kernel(const float* __restrict__ emb) {
    int gtid = blockIdx.x * blockDim.x + threadIdx.x;
    int warp = gtid >> 5;
    int lane = gtid & 31;
    if (warp < NROW) {
        const float4* row = reinterpret_cast<const float4*>(emb + (size_t)warp * DDIM);
        float4 v = row[lane];                       // 32 lanes x float4 = 128 floats
        float ss = v.x * v.x + v.y * v.y + v.z * v.z + v.w * v.w;
        #pragma unroll
        for (int off = 16; off; off >>= 1)
            ss += __shfl_xor_sync(0xffffffffu, ss, off);
        float nrm = fmaxf(sqrtf(ss), 1e-12f);
        float inv = 1.0f / nrm;
        float4 o = make_float4(v.x * inv, v.y * inv, v.z * inv, v.w * inv);
        reinterpret_cast<float4*>(g_eN + (size_t)warp * DDIM)[lane] = o;
    }
    if (gtid < NROW) {
        g_sumexp[gtid] = 0.0f;
        g_possum[gtid] = 0.0f;
        g_npos[gtid]   = 0.0f;
    }
}

// Swizzled smem layout in float4 units: row-major rows of 32 float4, with the
// 16B block index XOR-permuted by (row>>2) -> conflict-free STS.128 and
// cheap LDS in the mainloop.
__device__ __forceinline__ int swz(int row, int kb) {
    return row * 32 + (kb ^ (row >> 2));
}

// ---------------------------------------------------------------------------
// Kernel 2: fused tiled GEMM (e @ e^T / T) + streaming logsumexp/positive sums
// grid = (NCHUNK, NROW/BM); each CTA: one 128-row block x (128/NCHUNK) col tiles
// ---------------------------------------------------------------------------
__global__ __launch_bounds__(256, 2) void sim_kernel() {
    extern __shared__ float4 smem4[];
    float4* As4 = smem4;              // BM rows x 32 float4  (64 KB)
    float4* Bs4 = smem4 + BM * 32;    // BN rows x 32 float4  (32 KB)

    const int tid = threadIdx.x;
    const int tx = tid & 15;          // 16 threads over BN (TN=4 each)
    const int ty = tid >> 4;          // 16 threads over BM (TM=8 each)
    const int i0 = blockIdx.y * BM;

    const float4* eN4 = reinterpret_cast<const float4*>(g_eN);

    // Load A tile (BM x 128) once. Coalesced gmem float4, swizzled STS.
    for (int idx = tid; idx < BM * 32; idx += 256) {
        int r = idx >> 5, kc = idx & 31;
        As4[swz(r, kc)] = eN4[(size_t)(i0 + r) * 32 + kc];
    }

    int labi[TM];
    #pragma unroll
    for (int mi = 0; mi < TM; ++mi) labi[mi] = g_lab[i0 + ty * TM + mi];

    float se[TM], ps[TM], np[TM];
    #pragma unroll
    for (int mi = 0; mi < TM; ++mi) { se[mi] = 0.0f; ps[mi] = 0.0f; np[mi] = 0.0f; }

    for (int ct = blockIdx.x; ct < NROW / BN; ct += NCHUNK) {
        const int j0 = ct * BN;
        __syncthreads();  // previous tile's compute done before overwriting Bs
        for (int idx = tid; idx < BN * 32; idx += 256) {
            int r = idx >> 5, kc = idx & 31;
            Bs4[swz(r, kc)] = eN4[(size_t)(j0 + r) * 32 + kc];
        }
        __syncthreads();

        float acc[TM][TN];
        #pragma unroll
        for (int mi = 0; mi < TM; ++mi)
            #pragma unroll
            for (int ni = 0; ni < TN; ++ni) acc[mi][ni] = 0.0f;

        #pragma unroll 2
        for (int kb = 0; kb < 32; ++kb) {
            float4 b4[TN];
            #pragma unroll
            for (int ni = 0; ni < TN; ++ni)
                b4[ni] = Bs4[swz(tx * TN + ni, kb)];
            #pragma unroll
            for (int mi = 0; mi < TM; ++mi) {
                float4 a4 = As4[swz(ty * TM + mi, kb)];   // broadcast across warp
                #pragma unroll
                for (int ni = 0; ni < TN; ++ni) {
                    acc[mi][ni] += a4.x * b4[ni].x;
                    acc[mi][ni] += a4.y * b4[ni].y;
                    acc[mi][ni] += a4.z * b4[ni].z;
                    acc[mi][ni] += a4.w * b4[ni].w;
                }
            }
        }

        // Epilogue: sim = dot/T; accumulate exp-sum (excl. diagonal) + positives
        #pragma unroll
        for (int ni = 0; ni < TN; ++ni) {
            const int gj = j0 + tx * TN + ni;
            const int labj = g_lab[gj];
            #pragma unroll
            for (int mi = 0; mi < TM; ++mi) {
                const int gi = i0 + ty * TM + mi;
                float s = acc[mi][ni] * INV_T;
                if (gj != gi) {
                    se[mi] += __expf(s);                    // s <= 10, no overflow
                    if (labj == labi[mi]) { ps[mi] += s; np[mi] += 1.0f; }
                }
            }
        }
    }

    // Reduce across the 16 tx-threads (16-lane halves of each warp), then atomics
    #pragma unroll
    for (int mi = 0; mi < TM; ++mi) {
        #pragma unroll
        for (int off = 8; off; off >>= 1) {
            se[mi] += __shfl_xor_sync(0xffffffffu, se[mi], off);
            ps[mi] += __shfl_xor_sync(0xffffffffu, ps[mi], off);
            np[mi] += __shfl_xor_sync(0xffffffffu, np[mi], off);
        }
        if (tx == 0) {
            const int gi = i0 + ty * TM + mi;
            atomicAdd(&g_sumexp[gi], se[mi]);
            atomicAdd(&g_possum[gi], ps[mi]);
            atomicAdd(&g_npos[gi],  np[mi]);
        }
    }
}

// ---------------------------------------------------------------------------
// Kernel 3: loss_i = npos_i * log(sumexp_i) - possum_i; out = sum / N
// ---------------------------------------------------------------------------
__global__ void finalize_kernel(float* __restrict__ out) {
    __shared__ float red[32];
    const int tid = threadIdx.x;
    float acc = 0.0f;
    for (int i = tid; i < NROW; i += 1024)
        acc += g_npos[i] * logf(g_sumexp[i]) - g_possum[i];
    #pragma unroll
    for (int off = 16; off; off >>= 1)
        acc += __shfl_xor_sync(0xffffffffu, acc, off);
    if ((tid & 31) == 0) red[tid >> 5] = acc;
    __syncthreads();
    if (tid < 32) {
        float v = red[tid];
        #pragma unroll
        for (int off = 16; off; off >>= 1)
            v += __shfl_xor_sync(0xffffffffu, v, off);
        if (tid == 0) out[0] = v / (float)NROW;
    }
}

extern "C" void kernel_launch(void* const* d_in, const int* in_sizes, int n_in,
                              void* d_out, int out_size) {
    const float* emb = (const float*)d_in[0];
    const int* lab   = (const int*)d_in[1];   // raw words; dtype sniffed on device
    float* out       = (float*)d_out;

    const int smem_bytes = (BM + BN) * 32 * sizeof(float4);  // 98304
    cudaFuncSetAttribute(sim_kernel, cudaFuncAttributeMaxDynamicSharedMemorySize,
                         smem_bytes);

    labels_kernel<<<1, 1024>>>(lab);
    prep_kernel<<<NROW / 8, 256>>>(emb);
    sim_kernel<<<dim3(NCHUNK, NROW / BM), 256, smem_bytes>>>();
    finalize_kernel<<<1, 1024>>>(out);
}

// round 5
// speedup vs baseline: 2.2228x; 2.2228x over previous
#include <cuda_runtime.h>
#include <cuda_bf16.h>
#include <cstdint>

#define NROW 8192
#define DDIM 128
#define BM 128
#define BN 128
#define TILES 32          // j-tiles per CTA (jchunk = 4096 cols)
#define JCHUNK 4096
#define TEN_LOG2E 14.4269504088896f   // 10 * log2(e)

// -------------------- device globals (no allocations allowed) ---------------
__device__ __align__(256) __nv_bfloat16 g_eH[NROW * 256]; // row: [hi(128)|lo(128)]
__device__ __align__(256) int g_lab[NROW];
__device__ float g_sumexp[NROW];
__device__ float g_possum[NROW];   // raw dot sums over positives (x10 at finalize)
__device__ float g_npos[NROW];

// -------------------- PTX helpers (base ISA only, no 'a' features) ----------
__device__ __forceinline__ uint32_t smem_u32(const void* p) {
    uint32_t a;
    asm("{ .reg .u64 t; cvta.to.shared.u64 t, %1; cvt.u32.u64 %0, t; }" : "=r"(a) : "l"(p));
    return a;
}
__device__ __forceinline__ float ex2f(float x) {
    float y; asm("ex2.approx.f32 %0, %1;" : "=f"(y) : "f"(x)); return y;
}
__device__ __forceinline__ void cp16(uint32_t dst, const void* src) {
    asm volatile("cp.async.cg.shared.global [%0], [%1], 16;" :: "r"(dst), "l"(src));
}
#define CP_COMMIT() asm volatile("cp.async.commit_group;" ::: "memory")
#define CP_WAIT1()  asm volatile("cp.async.wait_group 1;" ::: "memory")

__device__ __forceinline__ void ldsm4(uint32_t* r, uint32_t addr) {
    asm volatile("ldmatrix.sync.aligned.m8n8.x4.shared.b16 {%0,%1,%2,%3}, [%4];"
        : "=r"(r[0]), "=r"(r[1]), "=r"(r[2]), "=r"(r[3]) : "r"(addr));
}
__device__ __forceinline__ void ldsm2(uint32_t* r, uint32_t addr) {
    asm volatile("ldmatrix.sync.aligned.m8n8.x2.shared.b16 {%0,%1}, [%2];"
        : "=r"(r[0]), "=r"(r[1]) : "r"(addr));
}
__device__ __forceinline__ void mma16816(float* d, const uint32_t* a, const uint32_t* b) {
    asm volatile(
        "mma.sync.aligned.m16n8k16.row.col.f32.bf16.bf16.f32 "
        "{%0,%1,%2,%3}, {%4,%5,%6,%7}, {%8,%9}, {%0,%1,%2,%3};"
        : "+f"(d[0]), "+f"(d[1]), "+f"(d[2]), "+f"(d[3])
        : "r"(a[0]), "r"(a[1]), "r"(a[2]), "r"(a[3]), "r"(b[0]), "r"(b[1]));
}

// Tile layout: 128 rows x 512B (256 bf16 = [hi|lo]); 16B chunk c at physical
// chunk c ^ (row & 7)  -> conflict-free cp.async stores and ldmatrix reads.
__device__ __forceinline__ void load_tile(uint32_t dst, const __nv_bfloat16* g, int tid) {
    const char* gb = (const char*)g;
    #pragma unroll
    for (int it = 0; it < 16; ++it) {
        int q = tid + it * 256;         // 0..4095
        int r = q >> 5, c = q & 31;
        cp16(dst + r * 512 + ((c ^ (r & 7)) * 16), gb + r * 512 + c * 16);
    }
}

// ---------------------------------------------------------------------------
// Kernel 0: label dtype sniff (int32 vs int64) + convert; zero out[0]
// ---------------------------------------------------------------------------
__global__ void labels_kernel(const int* __restrict__ raw, float* __restrict__ out) {
    __shared__ int s_or;
    if (threadIdx.x == 0) { s_or = 0; out[0] = 0.0f; }
    __syncthreads();
    int local = 0;
    for (int i = threadIdx.x; i < NROW / 2; i += blockDim.x) local |= raw[2 * i + 1];
    if (local) atomicOr(&s_or, 1);
    __syncthreads();
    const bool is32 = (s_or != 0);
    for (int i = threadIdx.x; i < NROW; i += blockDim.x)
        g_lab[i] = is32 ? raw[i] : raw[2 * i];
}

// ---------------------------------------------------------------------------
// Kernel 1: L2-normalize + bf16 hi/lo split; zero accumulators
// ---------------------------------------------------------------------------
__global__ void prep_kernel(const float* __restrict__ emb) {
    int gtid = blockIdx.x * blockDim.x + threadIdx.x;
    int row = gtid >> 5;
    int lane = gtid & 31;
    if (row < NROW) {
        float4 v = reinterpret_cast<const float4*>(emb + (size_t)row * DDIM)[lane];
        float ss = v.x * v.x + v.y * v.y + v.z * v.z + v.w * v.w;
        #pragma unroll
        for (int off = 16; off; off >>= 1) ss += __shfl_xor_sync(0xffffffffu, ss, off);
        float inv = 1.0f / fmaxf(sqrtf(ss), 1e-12f);
        float e[4] = {v.x * inv, v.y * inv, v.z * inv, v.w * inv};
        __nv_bfloat16 hi[4], lo[4];
        #pragma unroll
        for (int q = 0; q < 4; ++q) {
            hi[q] = __float2bfloat16(e[q]);
            lo[q] = __float2bfloat16(e[q] - __bfloat162float(hi[q]));
        }
        __nv_bfloat16* dst = g_eH + (size_t)row * 256;
        *reinterpret_cast<uint2*>(dst + 4 * lane)       = *reinterpret_cast<uint2*>(hi);
        *reinterpret_cast<uint2*>(dst + 128 + 4 * lane) = *reinterpret_cast<uint2*>(lo);
    }
    if (gtid < NROW) { g_sumexp[gtid] = 0.f; g_possum[gtid] = 0.f; g_npos[gtid] = 0.f; }
}

// ---------------------------------------------------------------------------
// Kernel 2: HMMA (mma.sync bf16 hi/lo, K=384 effective) + fused epilogue
// grid = (2, 64): y = i-block (128 rows), x = j-chunk (4096 cols, 32 tiles)
// 8 warps: warp_m = wid&1 (64 rows), warp_n = wid>>1 (32 cols)
// ---------------------------------------------------------------------------
__global__ __launch_bounds__(256, 1) void sim_kernel() {
    extern __shared__ char smem[];
    const uint32_t sbase = smem_u32(smem);
    const uint32_t abase = (sbase + 1023) & ~1023u;
    const uint32_t offA = abase;
    const uint32_t offB0 = abase + 65536;
    const uint32_t offB1 = abase + 131072;
    const uint32_t offL0 = abase + 196608;
    const uint32_t offL1 = abase + 197120;
    const int* labS0 = (const int*)(smem + (offL0 - sbase));
    const int* labS1 = (const int*)(smem + (offL1 - sbase));

    const int tid = threadIdx.x, lane = tid & 31, wid = tid >> 5;
    const int wm = wid & 1, wn = wid >> 1;
    const int i0 = blockIdx.y * BM;
    const int jbase = blockIdx.x * JCHUNK;

    // prologue loads: group0 = A + B(0) + lab(0); group1 = B(1) + lab(1)
    load_tile(offA, g_eH + (size_t)i0 * 256, tid);
    load_tile(offB0, g_eH + (size_t)jbase * 256, tid);
    if (tid < 32) cp16(offL0 + tid * 16, (const char*)(g_lab + jbase) + tid * 16);
    CP_COMMIT();
    load_tile(offB1, g_eH + (size_t)(jbase + BN) * 256, tid);
    if (tid < 32) cp16(offL1 + tid * 16, (const char*)(g_lab + jbase + BN) + tid * 16);
    CP_COMMIT();

    // per-thread fragment addressing
    const int asw = lane & 7;
    const uint32_t aRow = offA + (wm * 64 + (lane & 15)) * 512;   // ldmatrix.x4 rows
    const int ahalf = lane >> 4;                                   // chunk +0/+1
    const int bhalf = (lane >> 3) & 1;
    const uint32_t bRowOff = (wn * 32 + (lane & 7)) * 512;

    // this thread's 8 output rows and labels
    int labi[8];
    #pragma unroll
    for (int x = 0; x < 8; ++x)
        labi[x] = g_lab[i0 + wm * 64 + (x >> 1) * 16 + (x & 1) * 8 + (lane >> 2)];

    float se[8], ps[8], np[8];
    #pragma unroll
    for (int x = 0; x < 8; ++x) { se[x] = 0.f; ps[x] = 0.f; np[x] = 0.f; }

    // hi/lo pass regions (chunk base 0 = hi, 16 = lo): (hi,hi),(hi,lo),(lo,hi)
    const int AR[3] = {0, 0, 16}, BR[3] = {0, 16, 0};

    for (int t = 0; t < TILES; ++t) {
        CP_WAIT1();            // exactly one newer group (tile t+1) may remain
        __syncthreads();

        const uint32_t bBuf = (t & 1) ? offB1 : offB0;
        const uint32_t bRow = bBuf + bRowOff;

        float acc[4][4][4];
        #pragma unroll
        for (int mi = 0; mi < 4; ++mi)
            #pragma unroll
            for (int ni = 0; ni < 4; ++ni)
                #pragma unroll
                for (int q = 0; q < 4; ++q) acc[mi][ni][q] = 0.f;

        #pragma unroll
        for (int p = 0; p < 3; ++p) {
            #pragma unroll
            for (int ks = 0; ks < 8; ++ks) {
                const int cpa = AR[p] + ks * 2;
                const int cpb = BR[p] + ks * 2;
                uint32_t a[4][4], b[4][2];
                #pragma unroll
                for (int mi = 0; mi < 4; ++mi)
                    ldsm4(a[mi], aRow + mi * 8192 + (((cpa + ahalf) ^ asw) * 16));
                #pragma unroll
                for (int ni = 0; ni < 4; ++ni)
                    ldsm2(b[ni], bRow + ni * 4096 + (((cpb + bhalf) ^ asw) * 16));
                #pragma unroll
                for (int mi = 0; mi < 4; ++mi)
                    #pragma unroll
                    for (int ni = 0; ni < 4; ++ni)
                        mma16816(acc[mi][ni], a[mi], b[ni]);
            }
        }

        // fused epilogue from register accumulators
        const int j0 = jbase + t * BN;
        const bool diag = (j0 == i0);
        const int* labt = (t & 1) ? labS1 : labS0;
        #pragma unroll
        for (int ni = 0; ni < 4; ++ni) {
            const int colb = wn * 32 + ni * 8 + 2 * (lane & 3);
            const int lj0 = labt[colb], lj1 = labt[colb + 1];
            const int gj0 = j0 + colb, gj1 = gj0 + 1;
            #pragma unroll
            for (int mi = 0; mi < 4; ++mi) {
                const int gi0 = i0 + wm * 64 + mi * 16 + (lane >> 2);
                const int gi1 = gi0 + 8;
                const float* d = acc[mi][ni];
                if (!(diag && gi0 == gj0)) {
                    se[mi * 2] += ex2f(d[0] * TEN_LOG2E);
                    if (lj0 == labi[mi * 2]) { ps[mi * 2] += d[0]; np[mi * 2] += 1.f; }
                }
                if (!(diag && gi0 == gj1)) {
                    se[mi * 2] += ex2f(d[1] * TEN_LOG2E);
                    if (lj1 == labi[mi * 2]) { ps[mi * 2] += d[1]; np[mi * 2] += 1.f; }
                }
                if (!(diag && gi1 == gj0)) {
                    se[mi * 2 + 1] += ex2f(d[2] * TEN_LOG2E);
                    if (lj0 == labi[mi * 2 + 1]) { ps[mi * 2 + 1] += d[2]; np[mi * 2 + 1] += 1.f; }
                }
                if (!(diag && gi1 == gj1)) {
                    se[mi * 2 + 1] += ex2f(d[3] * TEN_LOG2E);
                    if (lj1 == labi[mi * 2 + 1]) { ps[mi * 2 + 1] += d[3]; np[mi * 2 + 1] += 1.f; }
                }
            }
        }

        __syncthreads();       // all warps done reading buf (t&1) and labels
        if (t + 2 < TILES) {
            const uint32_t nb = (t & 1) ? offB1 : offB0;   // same parity as t
            load_tile(nb, g_eH + (size_t)(jbase + (t + 2) * BN) * 256, tid);
            const uint32_t nl = (t & 1) ? offL1 : offL0;
            if (tid < 32)
                cp16(nl + tid * 16, (const char*)(g_lab + jbase + (t + 2) * BN) + tid * 16);
        }
        CP_COMMIT();           // always commit -> uniform group counting
    }

    // reduce across the 4 lanes of each quad (same rows), then atomics
    #pragma unroll
    for (int x = 0; x < 8; ++x) {
        float s = se[x], p = ps[x], n = np[x];
        s += __shfl_xor_sync(0xffffffffu, s, 1);
        s += __shfl_xor_sync(0xffffffffu, s, 2);
        p += __shfl_xor_sync(0xffffffffu, p, 1);
        p += __shfl_xor_sync(0xffffffffu, p, 2);
        n += __shfl_xor_sync(0xffffffffu, n, 1);
        n += __shfl_xor_sync(0xffffffffu, n, 2);
        if ((lane & 3) == 0) {
            const int gi = i0 + wm * 64 + (x >> 1) * 16 + (x & 1) * 8 + (lane >> 2);
            atomicAdd(&g_sumexp[gi], s);
            atomicAdd(&g_possum[gi], p);
            atomicAdd(&g_npos[gi],  n);
        }
    }
}

// ---------------------------------------------------------------------------
// Kernel 3: loss_i = npos_i*log(sumexp_i) - 10*possum_i; out = sum/N (atomic)
// ---------------------------------------------------------------------------
__global__ void finalize_kernel(float* __restrict__ out) {
    __shared__ float red[8];
    const int i = blockIdx.x * 256 + threadIdx.x;
    const int lane = threadIdx.x & 31, w = threadIdx.x >> 5;
    float v = g_npos[i] * logf(g_sumexp[i]) - 10.0f * g_possum[i];
    #pragma unroll
    for (int off = 16; off; off >>= 1) v += __shfl_xor_sync(0xffffffffu, v, off);
    if (lane == 0) red[w] = v;
    __syncthreads();
    if (threadIdx.x < 8) {
        float s = red[threadIdx.x];
        #pragma unroll
        for (int off = 4; off; off >>= 1) s += __shfl_xor_sync(0xffu, s, off);
        if (threadIdx.x == 0) atomicAdd(out, s / (float)NROW);
    }
}

extern "C" void kernel_launch(void* const* d_in, const int* in_sizes, int n_in,
                              void* d_out, int out_size) {
    const float* emb = (const float*)d_in[0];
    const int* lab   = (const int*)d_in[1];    // dtype sniffed on device
    float* out       = (float*)d_out;

    const int smem_bytes = 1024 + 3 * 65536 + 2048;  // 199680
    cudaFuncSetAttribute(sim_kernel, cudaFuncAttributeMaxDynamicSharedMemorySize,
                         smem_bytes);

    labels_kernel<<<1, 1024>>>(lab, out);
    prep_kernel<<<NROW / 8, 256>>>(emb);
    sim_kernel<<<dim3(2, 64), 256, smem_bytes>>>();
    finalize_kernel<<<32, 256>>>(out);
}

// round 6
// speedup vs baseline: 3.8837x; 1.7472x over previous
#include <cuda_runtime.h>
#include <cuda_bf16.h>
#include <cstdint>

#define NROW 8192
#define NTILE 64                     // 64x64 grid of 128x128 tiles
#define TOTUNITS (NTILE * NTILE)
#define TEN_LOG2E 14.4269504088896f  // 10 * log2(e)

// -------------------- device globals (no allocations allowed) ---------------
__device__ __align__(256) float g_eN[NROW * 128];  // normalized, tf32-rounded
__device__ __align__(256) int g_lab[NROW];
__device__ float g_sumexp[NROW];
__device__ float g_possum[NROW];   // raw dot sums over positives (x10 at finalize)
__device__ float g_npos[NROW];

// -------------------- PTX helpers (base ISA only) ---------------------------
__device__ __forceinline__ uint32_t smem_u32(const void* p) {
    uint32_t a;
    asm("{ .reg .u64 t; cvta.to.shared.u64 t, %1; cvt.u32.u64 %0, t; }" : "=r"(a) : "l"(p));
    return a;
}
__device__ __forceinline__ float ex2f(float x) {
    float y; asm("ex2.approx.f32 %0, %1;" : "=f"(y) : "f"(x)); return y;
}
__device__ __forceinline__ void cp16(uint32_t dst, const void* src) {
    asm volatile("cp.async.cg.shared.global [%0], [%1], 16;" :: "r"(dst), "l"(src));
}
#define CP_COMMIT() asm volatile("cp.async.commit_group;" ::: "memory")
#define CP_WAIT1()  asm volatile("cp.async.wait_group 1;" ::: "memory")

__device__ __forceinline__ void ldsm4(uint32_t* r, uint32_t addr) {
    asm volatile("ldmatrix.sync.aligned.m8n8.x4.shared.b16 {%0,%1,%2,%3}, [%4];"
        : "=r"(r[0]), "=r"(r[1]), "=r"(r[2]), "=r"(r[3]) : "r"(addr));
}
__device__ __forceinline__ uint32_t lds32(uint32_t addr) {
    uint32_t v; asm volatile("ld.shared.b32 %0, [%1];" : "=r"(v) : "r"(addr)); return v;
}
__device__ __forceinline__ void mma1688(float* d, const uint32_t* a, const uint32_t* b) {
    asm volatile(
        "mma.sync.aligned.m16n8k8.row.col.f32.tf32.tf32.f32 "
        "{%0,%1,%2,%3}, {%4,%5,%6,%7}, {%8,%9}, {%0,%1,%2,%3};"
        : "+f"(d[0]), "+f"(d[1]), "+f"(d[2]), "+f"(d[3])
        : "r"(a[0]), "r"(a[1]), "r"(a[2]), "r"(a[3]), "r"(b[0]), "r"(b[1]));
}

// Tile: 128 rows x 512B (128 fp32). 16B chunk c stored at c ^ (row & 7):
// conflict-free cp.async stores, ldmatrix reads, and per-thread B loads.
__device__ __forceinline__ void load_tile(uint32_t dst, const float* g, int tid) {
    const char* gb = (const char*)g;
    #pragma unroll
    for (int it = 0; it < 16; ++it) {
        int q = tid + it * 256;          // 0..4095
        int r = q >> 5, c = q & 31;
        cp16(dst + r * 512 + ((c ^ (r & 7)) * 16), gb + r * 512 + c * 16);
    }
}

// ---------------------------------------------------------------------------
// Kernel 0: label dtype sniff (int32 vs int64) + convert; zero out[0]
// ---------------------------------------------------------------------------
__global__ void labels_kernel(const int* __restrict__ raw, float* __restrict__ out) {
    __shared__ int s_or;
    if (threadIdx.x == 0) { s_or = 0; out[0] = 0.0f; }
    __syncthreads();
    int local = 0;
    for (int i = threadIdx.x; i < NROW / 2; i += blockDim.x) local |= raw[2 * i + 1];
    if (local) atomicOr(&s_or, 1);
    __syncthreads();
    const bool is32 = (s_or != 0);
    for (int i = threadIdx.x; i < NROW; i += blockDim.x)
        g_lab[i] = is32 ? raw[i] : raw[2 * i];
}

// ---------------------------------------------------------------------------
// Kernel 1: L2-normalize + tf32 round (cvt.rna); zero accumulators
// ---------------------------------------------------------------------------
__global__ void prep_kernel(const float* __restrict__ emb) {
    int gtid = blockIdx.x * blockDim.x + threadIdx.x;
    int row = gtid >> 5;
    int lane = gtid & 31;
    if (row < NROW) {
        float4 v = reinterpret_cast<const float4*>(emb + (size_t)row * 128)[lane];
        float ss = v.x * v.x + v.y * v.y + v.z * v.z + v.w * v.w;
        #pragma unroll
        for (int off = 16; off; off >>= 1) ss += __shfl_xor_sync(0xffffffffu, ss, off);
        float inv = 1.0f / fmaxf(sqrtf(ss), 1e-12f);
        float e[4] = {v.x * inv, v.y * inv, v.z * inv, v.w * inv};
        uint32_t t[4];
        #pragma unroll
        for (int q = 0; q < 4; ++q)
            asm("cvt.rna.tf32.f32 %0, %1;" : "=r"(t[q]) : "f"(e[q]));
        reinterpret_cast<uint4*>(g_eN + (size_t)row * 128)[lane] =
            make_uint4(t[0], t[1], t[2], t[3]);
    }
    if (gtid < NROW) { g_sumexp[gtid] = 0.f; g_possum[gtid] = 0.f; g_npos[gtid] = 0.f; }
}

// ---------------------------------------------------------------------------
// Kernel 2: persistent tf32 HMMA + fused epilogue.
// grid = #SMs; flat unit w = iblk*64 + jt over 64x64 tiles, j-major (A reuse).
// 8 warps: wm = wid&1 (64 rows), wn = wid>>1 (32 cols); warp tile 64x32.
// ---------------------------------------------------------------------------
__global__ __launch_bounds__(256, 1) void sim_kernel() {
    extern __shared__ char smem[];
    const uint32_t sbase = smem_u32(smem);
    const uint32_t abase = (sbase + 1023) & ~1023u;
    const uint32_t offA = abase;
    const uint32_t offB[2] = {abase + 65536, abase + 131072};
    const uint32_t offL[2] = {abase + 196608, abase + 197120};

    const int tid = threadIdx.x, lane = tid & 31, wid = tid >> 5;
    const int wm = wid & 1, wn = wid >> 1;

    // fragment addressing (tf32 m16n8k8 layouts)
    const uint32_t aRow = offA + (wm * 64 + (lane & 15)) * 512;
    const int aHi = lane >> 4, aXor = lane & 7;      // A chunk = (2ks + aHi) ^ aXor
    const uint32_t bColOff = ((wn * 32 + (lane >> 2)) * 512) + (lane & 3) * 4;
    const int bXor = lane >> 2;                      // B chunk = (2ks + h) ^ bXor

    const int G = gridDim.x, cta = blockIdx.x;
    int u  = (cta * TOTUNITS) / G;
    const int w1 = ((cta + 1) * TOTUNITS) / G;

    while (u < w1) {
        const int iblk = u >> 6;
        const int wend = min(w1, (iblk + 1) << 6);   // constant-i segment
        const int i0 = iblk * 128;

        // segment prologue: A + B(u) [+labels], then B(u+1)
        load_tile(offA, g_eN + (size_t)i0 * 128, tid);
        load_tile(offB[u & 1], g_eN + (size_t)((u & 63) * 128) * 128, tid);
        if (tid < 32) cp16(offL[u & 1] + tid * 16,
                           (const char*)(g_lab + (u & 63) * 128) + tid * 16);
        CP_COMMIT();
        if (u + 1 < wend) {
            load_tile(offB[(u + 1) & 1], g_eN + (size_t)(((u + 1) & 63) * 128) * 128, tid);
            if (tid < 32) cp16(offL[(u + 1) & 1] + tid * 16,
                               (const char*)(g_lab + ((u + 1) & 63) * 128) + tid * 16);
        }
        CP_COMMIT();

        int labi[8];
        #pragma unroll
        for (int x = 0; x < 8; ++x)
            labi[x] = g_lab[i0 + wm * 64 + (x >> 1) * 16 + (x & 1) * 8 + (lane >> 2)];

        float se[8], ps[8], np[8];
        #pragma unroll
        for (int x = 0; x < 8; ++x) { se[x] = 0.f; ps[x] = 0.f; np[x] = 0.f; }

        for (int v = u; v < wend; ++v) {
            CP_WAIT1();            // B(v)+lab(v) resident; B(v+1) may be in flight
            __syncthreads();

            const uint32_t bBuf = offB[v & 1];
            float acc[4][4][4];
            #pragma unroll
            for (int mi = 0; mi < 4; ++mi)
                #pragma unroll
                for (int ni = 0; ni < 4; ++ni)
                    #pragma unroll
                    for (int q = 0; q < 4; ++q) acc[mi][ni][q] = 0.f;

            #pragma unroll
            for (int ks = 0; ks < 16; ++ks) {
                uint32_t a[4][4], b[4][2];
                #pragma unroll
                for (int mi = 0; mi < 4; ++mi)
                    ldsm4(a[mi], aRow + mi * 8192 + (((2 * ks + aHi) ^ aXor) << 4));
                #pragma unroll
                for (int ni = 0; ni < 4; ++ni) {
                    const uint32_t base = bBuf + bColOff + ni * 4096;
                    b[ni][0] = lds32(base + (((2 * ks)     ^ bXor) << 4));
                    b[ni][1] = lds32(base + (((2 * ks + 1) ^ bXor) << 4));
                }
                #pragma unroll
                for (int mi = 0; mi < 4; ++mi)
                    #pragma unroll
                    for (int ni = 0; ni < 4; ++ni)
                        mma1688(acc[mi][ni], a[mi], b[ni]);
            }

            // stage this tile's column labels to registers (before buffer reuse)
            const int* labS = (const int*)(smem + (offL[v & 1] - sbase));
            int lj[4][2];
            #pragma unroll
            for (int ni = 0; ni < 4; ++ni) {
                const int colb = wn * 32 + ni * 8 + 2 * (lane & 3);
                lj[ni][0] = labS[colb];
                lj[ni][1] = labS[colb + 1];
            }
            __syncthreads();       // all warps done with B(v)/lab(v) smem

            if (v + 2 < wend) {    // prefetch before epilogue -> overlap
                load_tile(offB[v & 1], g_eN + (size_t)(((v + 2) & 63) * 128) * 128, tid);
                if (tid < 32) cp16(offL[v & 1] + tid * 16,
                                   (const char*)(g_lab + ((v + 2) & 63) * 128) + tid * 16);
            }
            CP_COMMIT();

            // register-only epilogue
            const int jt = v & 63;
            const int j0 = jt * 128;
            const bool diag = (jt == iblk);
            #pragma unroll
            for (int ni = 0; ni < 4; ++ni) {
                const int gj0 = j0 + wn * 32 + ni * 8 + 2 * (lane & 3);
                const int gj1 = gj0 + 1;
                const int lj0 = lj[ni][0], lj1 = lj[ni][1];
                #pragma unroll
                for (int mi = 0; mi < 4; ++mi) {
                    const int gi0 = i0 + wm * 64 + mi * 16 + (lane >> 2);
                    const int gi1 = gi0 + 8;
                    const float* d = acc[mi][ni];
                    if (!(diag && gi0 == gj0)) {
                        se[mi * 2] += ex2f(d[0] * TEN_LOG2E);
                        if (lj0 == labi[mi * 2]) { ps[mi * 2] += d[0]; np[mi * 2] += 1.f; }
                    }
                    if (!(diag && gi0 == gj1)) {
                        se[mi * 2] += ex2f(d[1] * TEN_LOG2E);
                        if (lj1 == labi[mi * 2]) { ps[mi * 2] += d[1]; np[mi * 2] += 1.f; }
                    }
                    if (!(diag && gi1 == gj0)) {
                        se[mi * 2 + 1] += ex2f(d[2] * TEN_LOG2E);
                        if (lj0 == labi[mi * 2 + 1]) { ps[mi * 2 + 1] += d[2]; np[mi * 2 + 1] += 1.f; }
                    }
                    if (!(diag && gi1 == gj1)) {
                        se[mi * 2 + 1] += ex2f(d[3] * TEN_LOG2E);
                        if (lj1 == labi[mi * 2 + 1]) { ps[mi * 2 + 1] += d[3]; np[mi * 2 + 1] += 1.f; }
                    }
                }
            }
        }

        // flush this segment's row accumulators (quad reduce + atomics)
        #pragma unroll
        for (int x = 0; x < 8; ++x) {
            float s = se[x], p = ps[x], n = np[x];
            s += __shfl_xor_sync(0xffffffffu, s, 1);
            s += __shfl_xor_sync(0xffffffffu, s, 2);
            p += __shfl_xor_sync(0xffffffffu, p, 1);
            p += __shfl_xor_sync(0xffffffffu, p, 2);
            n += __shfl_xor_sync(0xffffffffu, n, 1);
            n += __shfl_xor_sync(0xffffffffu, n, 2);
            if ((lane & 3) == 0) {
                const int gi = i0 + wm * 64 + (x >> 1) * 16 + (x & 1) * 8 + (lane >> 2);
                atomicAdd(&g_sumexp[gi], s);
                atomicAdd(&g_possum[gi], p);
                atomicAdd(&g_npos[gi],  n);
            }
        }
        u = wend;
    }
}

// ---------------------------------------------------------------------------
// Kernel 3: loss_i = npos_i*log(sumexp_i) - 10*possum_i; out = sum/N (atomic)
// ---------------------------------------------------------------------------
__global__ void finalize_kernel(float* __restrict__ out) {
    __shared__ float red[8];
    const int i = blockIdx.x * 256 + threadIdx.x;
    const int lane = threadIdx.x & 31, w = threadIdx.x >> 5;
    float v = g_npos[i] * logf(g_sumexp[i]) - 10.0f * g_possum[i];
    #pragma unroll
    for (int off = 16; off; off >>= 1) v += __shfl_xor_sync(0xffffffffu, v, off);
    if (lane == 0) red[w] = v;
    __syncthreads();
    if (threadIdx.x < 8) {
        float s = red[threadIdx.x];
        #pragma unroll
        for (int off = 4; off; off >>= 1) s += __shfl_xor_sync(0xffu, s, off);
        if (threadIdx.x == 0) atomicAdd(out, s / (float)NROW);
    }
}

extern "C" void kernel_launch(void* const* d_in, const int* in_sizes, int n_in,
                              void* d_out, int out_size) {
    const float* emb = (const float*)d_in[0];
    const int* lab   = (const int*)d_in[1];    // dtype sniffed on device
    float* out       = (float*)d_out;

    int nsm = 148;
    cudaDeviceGetAttribute(&nsm, cudaDevAttrMultiProcessorCount, 0);

    const int smem_bytes = 1024 + 3 * 65536 + 2048;  // 199680
    cudaFuncSetAttribute(sim_kernel, cudaFuncAttributeMaxDynamicSharedMemorySize,
                         smem_bytes);

    labels_kernel<<<1, 1024>>>(lab, out);
    prep_kernel<<<NROW / 8, 256>>>(emb);
    sim_kernel<<<nsm, 256, smem_bytes>>>();
    finalize_kernel<<<32, 256>>>(out);
}

// round 7
// speedup vs baseline: 6.4682x; 1.6655x over previous
#include <cuda_runtime.h>
#include <cuda_fp16.h>
#include <cstdint>

#define NROW 8192
#define NTILE 64                     // 64x64 grid of 128x128 tiles
#define TOTUNITS (NTILE * NTILE)
#define TEN_LOG2E 14.4269504088896f  // 10 * log2(e)

// -------------------- device globals (no allocations allowed) ---------------
__device__ __align__(256) __half g_eH[NROW * 128];  // normalized, fp16
__device__ __align__(256) int g_lab[NROW];
__device__ float g_sumexp[NROW];
__device__ float g_possum[NROW];   // raw dot sums over positives (x10 at finalize)
__device__ float g_npos[NROW];

// -------------------- PTX helpers (base ISA only) ---------------------------
__device__ __forceinline__ uint32_t smem_u32(const void* p) {
    uint32_t a;
    asm("{ .reg .u64 t; cvta.to.shared.u64 t, %1; cvt.u32.u64 %0, t; }" : "=r"(a) : "l"(p));
    return a;
}
__device__ __forceinline__ float ex2f(float x) {
    float y; asm("ex2.approx.f32 %0, %1;" : "=f"(y) : "f"(x)); return y;
}
__device__ __forceinline__ void cp16(uint32_t dst, const void* src) {
    asm volatile("cp.async.cg.shared.global [%0], [%1], 16;" :: "r"(dst), "l"(src));
}
#define CP_COMMIT() asm volatile("cp.async.commit_group;" ::: "memory")
#define CP_WAIT1()  asm volatile("cp.async.wait_group 1;" ::: "memory")

__device__ __forceinline__ void ldsm4(uint32_t* r, uint32_t addr) {
    asm volatile("ldmatrix.sync.aligned.m8n8.x4.shared.b16 {%0,%1,%2,%3}, [%4];"
        : "=r"(r[0]), "=r"(r[1]), "=r"(r[2]), "=r"(r[3]) : "r"(addr));
}
__device__ __forceinline__ void ldsm2(uint32_t* r, uint32_t addr) {
    asm volatile("ldmatrix.sync.aligned.m8n8.x2.shared.b16 {%0,%1}, [%2];"
        : "=r"(r[0]), "=r"(r[1]) : "r"(addr));
}
__device__ __forceinline__ void mma16816(float* d, const uint32_t* a, const uint32_t* b) {
    asm volatile(
        "mma.sync.aligned.m16n8k16.row.col.f32.f16.f16.f32 "
        "{%0,%1,%2,%3}, {%4,%5,%6,%7}, {%8,%9}, {%0,%1,%2,%3};"
        : "+f"(d[0]), "+f"(d[1]), "+f"(d[2]), "+f"(d[3])
        : "r"(a[0]), "r"(a[1]), "r"(a[2]), "r"(a[3]), "r"(b[0]), "r"(b[1]));
}

// Tile: 128 rows x 256B (128 fp16). 16B chunk c stored at c ^ (r & 7):
// conflict-free cp.async stores and ldmatrix reads.
__device__ __forceinline__ void load_tile(uint32_t dst, const __half* g, int tid) {
    const char* gb = (const char*)g;
    #pragma unroll
    for (int it = 0; it < 8; ++it) {
        int q = tid + it * 256;          // 0..2047
        int r = q >> 4, c = q & 15;
        cp16(dst + r * 256 + ((c ^ (r & 7)) * 16), gb + r * 256 + c * 16);
    }
}

// ---------------------------------------------------------------------------
// Kernel 0: label dtype sniff (int32 vs int64) + convert; zero out[0]
// ---------------------------------------------------------------------------
__global__ void labels_kernel(const int* __restrict__ raw, float* __restrict__ out) {
    __shared__ int s_or;
    if (threadIdx.x == 0) { s_or = 0; out[0] = 0.0f; }
    __syncthreads();
    int local = 0;
    for (int i = threadIdx.x; i < NROW / 2; i += blockDim.x) local |= raw[2 * i + 1];
    if (local) atomicOr(&s_or, 1);
    __syncthreads();
    const bool is32 = (s_or != 0);
    for (int i = threadIdx.x; i < NROW; i += blockDim.x)
        g_lab[i] = is32 ? raw[i] : raw[2 * i];
}

// ---------------------------------------------------------------------------
// Kernel 1: L2-normalize (fp32) + fp16 convert; zero accumulators
// ---------------------------------------------------------------------------
__global__ void prep_kernel(const float* __restrict__ emb) {
    int gtid = blockIdx.x * blockDim.x + threadIdx.x;
    int row = gtid >> 5;
    int lane = gtid & 31;
    if (row < NROW) {
        float4 v = reinterpret_cast<const float4*>(emb + (size_t)row * 128)[lane];
        float ss = v.x * v.x + v.y * v.y + v.z * v.z + v.w * v.w;
        #pragma unroll
        for (int off = 16; off; off >>= 1) ss += __shfl_xor_sync(0xffffffffu, ss, off);
        float inv = 1.0f / fmaxf(sqrtf(ss), 1e-12f);
        __half2 h0 = __floats2half2_rn(v.x * inv, v.y * inv);
        __half2 h1 = __floats2half2_rn(v.z * inv, v.w * inv);
        uint2 pk;
        pk.x = *reinterpret_cast<uint32_t*>(&h0);
        pk.y = *reinterpret_cast<uint32_t*>(&h1);
        reinterpret_cast<uint2*>(g_eH + (size_t)row * 128)[lane] = pk;
    }
    if (gtid < NROW) { g_sumexp[gtid] = 0.f; g_possum[gtid] = 0.f; g_npos[gtid] = 0.f; }
}

// ---------------------------------------------------------------------------
// Kernel 2: persistent fp16 HMMA (m16n8k16, single pass K=128) + fused epilogue
// grid = #SMs; flat unit w = iblk*64 + jt over 64x64 tiles, j-major (A reuse).
// 8 warps: wm = wid&1 (64 rows), wn = wid>>1 (32 cols); warp tile 64x32.
// ---------------------------------------------------------------------------
__global__ __launch_bounds__(256, 1) void sim_kernel() {
    extern __shared__ char smem[];
    const uint32_t sbase = smem_u32(smem);
    const uint32_t abase = (sbase + 1023) & ~1023u;
    const uint32_t offA = abase;
    const uint32_t offB[2] = {abase + 32768, abase + 65536};
    const uint32_t offL[2] = {abase + 98304, abase + 98816};

    const int tid = threadIdx.x, lane = tid & 31, wid = tid >> 5;
    const int wm = wid & 1, wn = wid >> 1;

    // fragment addressing (fp16 m16n8k16, validated layout from round 5)
    const int asw = lane & 7;
    const uint32_t aRow = offA + (wm * 64 + (lane & 15)) * 256;
    const int aHalf = lane >> 4;                  // A chunk = (2ks + aHalf) ^ asw
    const int bHalf = (lane >> 3) & 1;            // B chunk = (2ks + bHalf) ^ asw
    const uint32_t bRowOff = (wn * 32 + (lane & 7)) * 256;

    const int G = gridDim.x, cta = blockIdx.x;
    int u  = (cta * TOTUNITS) / G;
    const int w1 = ((cta + 1) * TOTUNITS) / G;

    while (u < w1) {
        const int iblk = u >> 6;
        const int wend = min(w1, (iblk + 1) << 6);   // constant-i segment
        const int i0 = iblk * 128;

        // segment prologue: A + B(u) + lab(u); then B(u+1) + lab(u+1)
        load_tile(offA, g_eH + (size_t)i0 * 128, tid);
        load_tile(offB[u & 1], g_eH + (size_t)((u & 63) * 128) * 128, tid);
        if (tid < 32) cp16(offL[u & 1] + tid * 16,
                           (const char*)(g_lab + (u & 63) * 128) + tid * 16);
        CP_COMMIT();
        if (u + 1 < wend) {
            load_tile(offB[(u + 1) & 1], g_eH + (size_t)(((u + 1) & 63) * 128) * 128, tid);
            if (tid < 32) cp16(offL[(u + 1) & 1] + tid * 16,
                               (const char*)(g_lab + ((u + 1) & 63) * 128) + tid * 16);
        }
        CP_COMMIT();

        int labi[8];
        #pragma unroll
        for (int x = 0; x < 8; ++x)
            labi[x] = g_lab[i0 + wm * 64 + (x >> 1) * 16 + (x & 1) * 8 + (lane >> 2)];

        float se[8], ps[8], np[8];
        #pragma unroll
        for (int x = 0; x < 8; ++x) { se[x] = 0.f; ps[x] = 0.f; np[x] = 0.f; }

        for (int v = u; v < wend; ++v) {
            CP_WAIT1();            // B(v)+lab(v) resident; B(v+1) may be in flight
            __syncthreads();

            const uint32_t bRow = offB[v & 1] + bRowOff;
            float acc[4][4][4];
            #pragma unroll
            for (int mi = 0; mi < 4; ++mi)
                #pragma unroll
                for (int ni = 0; ni < 4; ++ni)
                    #pragma unroll
                    for (int q = 0; q < 4; ++q) acc[mi][ni][q] = 0.f;

            #pragma unroll
            for (int ks = 0; ks < 8; ++ks) {
                uint32_t a[4][4], b[4][2];
                #pragma unroll
                for (int mi = 0; mi < 4; ++mi)
                    ldsm4(a[mi], aRow + mi * 4096 + (((2 * ks + aHalf) ^ asw) << 4));
                #pragma unroll
                for (int ni = 0; ni < 4; ++ni)
                    ldsm2(b[ni], bRow + ni * 2048 + (((2 * ks + bHalf) ^ asw) << 4));
                #pragma unroll
                for (int mi = 0; mi < 4; ++mi)
                    #pragma unroll
                    for (int ni = 0; ni < 4; ++ni)
                        mma16816(acc[mi][ni], a[mi], b[ni]);
            }

            // stage this tile's column labels to registers (before buffer reuse)
            const int* labS = (const int*)(smem + (offL[v & 1] - sbase));
            int lj[4][2];
            #pragma unroll
            for (int ni = 0; ni < 4; ++ni) {
                const int colb = wn * 32 + ni * 8 + 2 * (lane & 3);
                lj[ni][0] = labS[colb];
                lj[ni][1] = labS[colb + 1];
            }
            __syncthreads();       // all warps done with B(v)/lab(v) smem

            if (v + 2 < wend) {    // prefetch before epilogue -> overlap
                load_tile(offB[v & 1], g_eH + (size_t)(((v + 2) & 63) * 128) * 128, tid);
                if (tid < 32) cp16(offL[v & 1] + tid * 16,
                                   (const char*)(g_lab + ((v + 2) & 63) * 128) + tid * 16);
            }
            CP_COMMIT();

            // register-only epilogue; diagonal checks hoisted to a uniform branch
            const int jt = v & 63;
            if (jt != iblk) {
                #pragma unroll
                for (int ni = 0; ni < 4; ++ni) {
                    const int lj0 = lj[ni][0], lj1 = lj[ni][1];
                    #pragma unroll
                    for (int mi = 0; mi < 4; ++mi) {
                        const float* d = acc[mi][ni];
                        se[mi * 2] += ex2f(d[0] * TEN_LOG2E);
                        if (lj0 == labi[mi * 2]) { ps[mi * 2] += d[0]; np[mi * 2] += 1.f; }
                        se[mi * 2] += ex2f(d[1] * TEN_LOG2E);
                        if (lj1 == labi[mi * 2]) { ps[mi * 2] += d[1]; np[mi * 2] += 1.f; }
                        se[mi * 2 + 1] += ex2f(d[2] * TEN_LOG2E);
                        if (lj0 == labi[mi * 2 + 1]) { ps[mi * 2 + 1] += d[2]; np[mi * 2 + 1] += 1.f; }
                        se[mi * 2 + 1] += ex2f(d[3] * TEN_LOG2E);
                        if (lj1 == labi[mi * 2 + 1]) { ps[mi * 2 + 1] += d[3]; np[mi * 2 + 1] += 1.f; }
                    }
                }
            } else {
                const int j0 = jt * 128;
                #pragma unroll
                for (int ni = 0; ni < 4; ++ni) {
                    const int gj0 = j0 + wn * 32 + ni * 8 + 2 * (lane & 3);
                    const int gj1 = gj0 + 1;
                    const int lj0 = lj[ni][0], lj1 = lj[ni][1];
                    #pragma unroll
                    for (int mi = 0; mi < 4; ++mi) {
                        const int gi0 = i0 + wm * 64 + mi * 16 + (lane >> 2);
                        const int gi1 = gi0 + 8;
                        const float* d = acc[mi][ni];
                        if (gi0 != gj0) {
                            se[mi * 2] += ex2f(d[0] * TEN_LOG2E);
                            if (lj0 == labi[mi * 2]) { ps[mi * 2] += d[0]; np[mi * 2] += 1.f; }
                        }
                        if (gi0 != gj1) {
                            se[mi * 2] += ex2f(d[1] * TEN_LOG2E);
                            if (lj1 == labi[mi * 2]) { ps[mi * 2] += d[1]; np[mi * 2] += 1.f; }
                        }
                        if (gi1 != gj0) {
                            se[mi * 2 + 1] += ex2f(d[2] * TEN_LOG2E);
                            if (lj0 == labi[mi * 2 + 1]) { ps[mi * 2 + 1] += d[2]; np[mi * 2 + 1] += 1.f; }
                        }
                        if (gi1 != gj1) {
                            se[mi * 2 + 1] += ex2f(d[3] * TEN_LOG2E);
                            if (lj1 == labi[mi * 2 + 1]) { ps[mi * 2 + 1] += d[3]; np[mi * 2 + 1] += 1.f; }
                        }
                    }
                }
            }
        }

        // flush this segment's row accumulators (quad reduce + atomics)
        #pragma unroll
        for (int x = 0; x < 8; ++x) {
            float s = se[x], p = ps[x], n = np[x];
            s += __shfl_xor_sync(0xffffffffu, s, 1);
            s += __shfl_xor_sync(0xffffffffu, s, 2);
            p += __shfl_xor_sync(0xffffffffu, p, 1);
            p += __shfl_xor_sync(0xffffffffu, p, 2);
            n += __shfl_xor_sync(0xffffffffu, n, 1);
            n += __shfl_xor_sync(0xffffffffu, n, 2);
            if ((lane & 3) == 0) {
                const int gi = i0 + wm * 64 + (x >> 1) * 16 + (x & 1) * 8 + (lane >> 2);
                atomicAdd(&g_sumexp[gi], s);
                atomicAdd(&g_possum[gi], p);
                atomicAdd(&g_npos[gi],  n);
            }
        }
        u = wend;
    }
}

// ---------------------------------------------------------------------------
// Kernel 3: loss_i = npos_i*log(sumexp_i) - 10*possum_i; out = sum/N (atomic)
// ---------------------------------------------------------------------------
__global__ void finalize_kernel(float* __restrict__ out) {
    __shared__ float red[8];
    const int i = blockIdx.x * 256 + threadIdx.x;
    const int lane = threadIdx.x & 31, w = threadIdx.x >> 5;
    float v = g_npos[i] * logf(g_sumexp[i]) - 10.0f * g_possum[i];
    #pragma unroll
    for (int off = 16; off; off >>= 1) v += __shfl_xor_sync(0xffffffffu, v, off);
    if (lane == 0) red[w] = v;
    __syncthreads();
    if (threadIdx.x < 8) {
        float s = red[threadIdx.x];
        #pragma unroll
        for (int off = 4; off; off >>= 1) s += __shfl_xor_sync(0xffu, s, off);
        if (threadIdx.x == 0) atomicAdd(out, s / (float)NROW);
    }
}

extern "C" void kernel_launch(void* const* d_in, const int* in_sizes, int n_in,
                              void* d_out, int out_size) {
    const float* emb = (const float*)d_in[0];
    const int* lab   = (const int*)d_in[1];    // dtype sniffed on device
    float* out       = (float*)d_out;

    int nsm = 148;
    cudaDeviceGetAttribute(&nsm, cudaDevAttrMultiProcessorCount, 0);

    const int smem_bytes = 1024 + 3 * 32768 + 2048;  // 101376
    cudaFuncSetAttribute(sim_kernel, cudaFuncAttributeMaxDynamicSharedMemorySize,
                         smem_bytes);

    labels_kernel<<<1, 1024>>>(lab, out);
    prep_kernel<<<NROW / 8, 256>>>(emb);
    sim_kernel<<<nsm, 256, smem_bytes>>>();
    finalize_kernel<<<32, 256>>>(out);
}

// round 8
// speedup vs baseline: 7.8519x; 1.2139x over previous
#include <cuda_runtime.h>
#include <cuda_fp16.h>
#include <cstdint>

#define NROW 8192
#define NTILE 64                      // 64x64 logical tiles; upper triangle only
#define TOTUNITS 2080                 // 64*65/2
#define TEN_LOG2E 14.4269504088896f   // 10 * log2(e)

// -------------------- device globals (no allocations allowed) ---------------
__device__ __align__(256) __half g_eH[NROW * 128];  // normalized, fp16
__device__ __align__(256) int g_lab[NROW];
__device__ float g_sumexp[NROW];
__device__ float g_possum[NROW];   // raw dot sums over positives (x10 at finalize)
__device__ float g_npos[NROW];

// -------------------- PTX helpers (base ISA only) ---------------------------
__device__ __forceinline__ uint32_t smem_u32(const void* p) {
    uint32_t a;
    asm("{ .reg .u64 t; cvta.to.shared.u64 t, %1; cvt.u32.u64 %0, t; }" : "=r"(a) : "l"(p));
    return a;
}
__device__ __forceinline__ float ex2f(float x) {
    float y; asm("ex2.approx.f32 %0, %1;" : "=f"(y) : "f"(x)); return y;
}
__device__ __forceinline__ void cp16(uint32_t dst, const void* src) {
    asm volatile("cp.async.cg.shared.global [%0], [%1], 16;" :: "r"(dst), "l"(src));
}
#define CP_COMMIT() asm volatile("cp.async.commit_group;" ::: "memory")
#define CP_WAIT1()  asm volatile("cp.async.wait_group 1;" ::: "memory")

__device__ __forceinline__ void ldsm4(uint32_t* r, uint32_t addr) {
    asm volatile("ldmatrix.sync.aligned.m8n8.x4.shared.b16 {%0,%1,%2,%3}, [%4];"
        : "=r"(r[0]), "=r"(r[1]), "=r"(r[2]), "=r"(r[3]) : "r"(addr));
}
__device__ __forceinline__ void ldsm2(uint32_t* r, uint32_t addr) {
    asm volatile("ldmatrix.sync.aligned.m8n8.x2.shared.b16 {%0,%1}, [%2];"
        : "=r"(r[0]), "=r"(r[1]) : "r"(addr));
}
__device__ __forceinline__ void mma16816(float* d, const uint32_t* a, const uint32_t* b) {
    asm volatile(
        "mma.sync.aligned.m16n8k16.row.col.f32.f16.f16.f32 "
        "{%0,%1,%2,%3}, {%4,%5,%6,%7}, {%8,%9}, {%0,%1,%2,%3};"
        : "+f"(d[0]), "+f"(d[1]), "+f"(d[2]), "+f"(d[3])
        : "r"(a[0]), "r"(a[1]), "r"(a[2]), "r"(a[3]), "r"(b[0]), "r"(b[1]));
}

// Tile: 128 rows x 256B (128 fp16). 16B chunk c stored at c ^ (r & 7).
__device__ __forceinline__ void load_tile(uint32_t dst, const __half* g, int tid) {
    const char* gb = (const char*)g;
    #pragma unroll
    for (int it = 0; it < 8; ++it) {
        int q = tid + it * 256;          // 0..2047
        int r = q >> 4, c = q & 15;
        cp16(dst + r * 256 + ((c ^ (r & 7)) * 16), gb + r * 256 + c * 16);
    }
}

// triangular row offset: first flat unit of row bi (bi tiles bj in [bi, 64))
__device__ __forceinline__ int tri_off(int bi) { return bi * (129 - bi) / 2; }

// ---------------------------------------------------------------------------
// Kernel 0: label dtype sniff (int32 vs int64) + convert; zero out[0]
// 8 blocks, each sniffs independently (deterministic) and converts its slice.
// ---------------------------------------------------------------------------
__global__ void labels_kernel(const int* __restrict__ raw, float* __restrict__ out) {
    __shared__ int s_or;
    if (threadIdx.x == 0) { s_or = 0; if (blockIdx.x == 0) out[0] = 0.0f; }
    __syncthreads();
    int local = 0;
    for (int i = threadIdx.x; i < 2048; i += blockDim.x) local |= raw[2 * i + 1];
    if (local) atomicOr(&s_or, 1);
    __syncthreads();
    const bool is32 = (s_or != 0);
    const int base = blockIdx.x * (NROW / 8);
    for (int i = base + threadIdx.x; i < base + NROW / 8; i += blockDim.x)
        g_lab[i] = is32 ? raw[i] : raw[2 * i];
}

// ---------------------------------------------------------------------------
// Kernel 1: L2-normalize (fp32) + fp16 convert; zero accumulators
// ---------------------------------------------------------------------------
__global__ void prep_kernel(const float* __restrict__ emb) {
    int gtid = blockIdx.x * blockDim.x + threadIdx.x;
    int row = gtid >> 5;
    int lane = gtid & 31;
    if (row < NROW) {
        float4 v = reinterpret_cast<const float4*>(emb + (size_t)row * 128)[lane];
        float ss = v.x * v.x + v.y * v.y + v.z * v.z + v.w * v.w;
        #pragma unroll
        for (int off = 16; off; off >>= 1) ss += __shfl_xor_sync(0xffffffffu, ss, off);
        float inv = 1.0f / fmaxf(sqrtf(ss), 1e-12f);
        __half2 h0 = __floats2half2_rn(v.x * inv, v.y * inv);
        __half2 h1 = __floats2half2_rn(v.z * inv, v.w * inv);
        uint2 pk;
        pk.x = *reinterpret_cast<uint32_t*>(&h0);
        pk.y = *reinterpret_cast<uint32_t*>(&h1);
        reinterpret_cast<uint2*>(g_eH + (size_t)row * 128)[lane] = pk;
    }
    if (gtid < NROW) { g_sumexp[gtid] = 0.f; g_possum[gtid] = 0.f; g_npos[gtid] = 0.f; }
}

// ---------------------------------------------------------------------------
// Kernel 2: persistent fp16 HMMA over the UPPER TRIANGLE of the tile grid.
// Off-diagonal tile (bi,bj): registers hold sim[i,j]; accumulate row-side
// stats for rows i AND (by symmetry) column-side stats for rows j.
// Diagonal tile: row-side only with self-exclusion (entries appear once).
// ---------------------------------------------------------------------------
__global__ __launch_bounds__(256, 1) void sim_kernel() {
    extern __shared__ char smem[];
    const uint32_t sbase = smem_u32(smem);
    const uint32_t abase = (sbase + 1023) & ~1023u;
    const uint32_t offA = abase;
    const uint32_t offB[2] = {abase + 32768, abase + 65536};
    const uint32_t offL[2] = {abase + 98304, abase + 98816};

    const int tid = threadIdx.x, lane = tid & 31, wid = tid >> 5;
    const int wm = wid & 1, wn = wid >> 1;

    // fragment addressing (fp16 m16n8k16)
    const int asw = lane & 7;
    const uint32_t aRow = offA + (wm * 64 + (lane & 15)) * 256;
    const int aHalf = lane >> 4;
    const int bHalf = (lane >> 3) & 1;
    const uint32_t bRowOff = (wn * 32 + (lane & 7)) * 256;

    const int G = gridDim.x, cta = blockIdx.x;
    int u = (int)(((long long)cta * TOTUNITS) / G);
    const int w1 = (int)(((long long)(cta + 1) * TOTUNITS) / G);

    while (u < w1) {
        // decode row-block bi from flat triangular index u
        int bi = (int)((129.0 - sqrt(129.0 * 129.0 - 8.0 * (double)u)) * 0.5);
        while (tri_off(bi) > u) --bi;
        while (tri_off(bi + 1) <= u) ++bi;
        const int offbi = tri_off(bi);
        const int wend = min(w1, tri_off(bi + 1));
        const int i0 = bi * 128;

        // segment prologue: A + B(u)+lab(u); then B(u+1)+lab(u+1)
        load_tile(offA, g_eH + (size_t)i0 * 128, tid);
        {
            const int bj0 = bi + (u - offbi);
            load_tile(offB[u & 1], g_eH + (size_t)bj0 * 128 * 128, tid);
            if (tid < 32) cp16(offL[u & 1] + tid * 16,
                               (const char*)(g_lab + bj0 * 128) + tid * 16);
        }
        CP_COMMIT();
        if (u + 1 < wend) {
            const int bj1 = bi + (u + 1 - offbi);
            load_tile(offB[(u + 1) & 1], g_eH + (size_t)bj1 * 128 * 128, tid);
            if (tid < 32) cp16(offL[(u + 1) & 1] + tid * 16,
                               (const char*)(g_lab + bj1 * 128) + tid * 16);
        }
        CP_COMMIT();

        int labi[8];
        #pragma unroll
        for (int x = 0; x < 8; ++x)
            labi[x] = g_lab[i0 + wm * 64 + (x >> 1) * 16 + (x & 1) * 8 + (lane >> 2)];

        float se[8], ps[8], np[8];
        #pragma unroll
        for (int x = 0; x < 8; ++x) { se[x] = 0.f; ps[x] = 0.f; np[x] = 0.f; }

        for (int v = u; v < wend; ++v) {
            CP_WAIT1();
            __syncthreads();

            const uint32_t bRow = offB[v & 1] + bRowOff;
            float acc[4][4][4];
            #pragma unroll
            for (int mi = 0; mi < 4; ++mi)
                #pragma unroll
                for (int ni = 0; ni < 4; ++ni)
                    #pragma unroll
                    for (int q = 0; q < 4; ++q) acc[mi][ni][q] = 0.f;

            #pragma unroll
            for (int ks = 0; ks < 8; ++ks) {
                uint32_t a[4][4], b[4][2];
                #pragma unroll
                for (int mi = 0; mi < 4; ++mi)
                    ldsm4(a[mi], aRow + mi * 4096 + (((2 * ks + aHalf) ^ asw) << 4));
                #pragma unroll
                for (int ni = 0; ni < 4; ++ni)
                    ldsm2(b[ni], bRow + ni * 2048 + (((2 * ks + bHalf) ^ asw) << 4));
                #pragma unroll
                for (int mi = 0; mi < 4; ++mi)
                    #pragma unroll
                    for (int ni = 0; ni < 4; ++ni)
                        mma16816(acc[mi][ni], a[mi], b[ni]);
            }

            // stage this tile's column labels to registers
            const int* labS = (const int*)(smem + (offL[v & 1] - sbase));
            int lj[4][2];
            #pragma unroll
            for (int ni = 0; ni < 4; ++ni) {
                const int colb = wn * 32 + ni * 8 + 2 * (lane & 3);
                lj[ni][0] = labS[colb];
                lj[ni][1] = labS[colb + 1];
            }
            __syncthreads();

            if (v + 2 < wend) {
                const int bjn = bi + (v + 2 - offbi);
                load_tile(offB[v & 1], g_eH + (size_t)bjn * 128 * 128, tid);
                if (tid < 32) cp16(offL[v & 1] + tid * 16,
                                   (const char*)(g_lab + bjn * 128) + tid * 16);
            }
            CP_COMMIT();

            const int bj = bi + (v - offbi);
            if (bj != bi) {
                // off-diagonal: row-side + symmetric column-side
                float ce[4][2], cp[4][2], cn[4][2];
                #pragma unroll
                for (int ni = 0; ni < 4; ++ni)
                    #pragma unroll
                    for (int h = 0; h < 2; ++h) { ce[ni][h] = 0.f; cp[ni][h] = 0.f; cn[ni][h] = 0.f; }

                #pragma unroll
                for (int ni = 0; ni < 4; ++ni) {
                    const int lj0 = lj[ni][0], lj1 = lj[ni][1];
                    #pragma unroll
                    for (int mi = 0; mi < 4; ++mi) {
                        const float* d = acc[mi][ni];
                        float e0 = ex2f(d[0] * TEN_LOG2E);
                        se[mi * 2] += e0; ce[ni][0] += e0;
                        if (lj0 == labi[mi * 2]) {
                            ps[mi * 2] += d[0]; np[mi * 2] += 1.f;
                            cp[ni][0] += d[0]; cn[ni][0] += 1.f;
                        }
                        float e1 = ex2f(d[1] * TEN_LOG2E);
                        se[mi * 2] += e1; ce[ni][1] += e1;
                        if (lj1 == labi[mi * 2]) {
                            ps[mi * 2] += d[1]; np[mi * 2] += 1.f;
                            cp[ni][1] += d[1]; cn[ni][1] += 1.f;
                        }
                        float e2 = ex2f(d[2] * TEN_LOG2E);
                        se[mi * 2 + 1] += e2; ce[ni][0] += e2;
                        if (lj0 == labi[mi * 2 + 1]) {
                            ps[mi * 2 + 1] += d[2]; np[mi * 2 + 1] += 1.f;
                            cp[ni][0] += d[2]; cn[ni][0] += 1.f;
                        }
                        float e3 = ex2f(d[3] * TEN_LOG2E);
                        se[mi * 2 + 1] += e3; ce[ni][1] += e3;
                        if (lj1 == labi[mi * 2 + 1]) {
                            ps[mi * 2 + 1] += d[3]; np[mi * 2 + 1] += 1.f;
                            cp[ni][1] += d[3]; cn[ni][1] += 1.f;
                        }
                    }
                }
                // reduce col partials across the 8 lanes sharing each column
                #pragma unroll
                for (int ni = 0; ni < 4; ++ni)
                    #pragma unroll
                    for (int h = 0; h < 2; ++h) {
                        float a0 = ce[ni][h], a1 = cp[ni][h], a2 = cn[ni][h];
                        #pragma unroll
                        for (int off = 4; off <= 16; off <<= 1) {
                            a0 += __shfl_xor_sync(0xffffffffu, a0, off);
                            a1 += __shfl_xor_sync(0xffffffffu, a1, off);
                            a2 += __shfl_xor_sync(0xffffffffu, a2, off);
                        }
                        ce[ni][h] = a0; cp[ni][h] = a1; cn[ni][h] = a2;
                    }
                if (lane < 4) {
                    const int cbase = bj * 128 + wn * 32 + 2 * lane;
                    #pragma unroll
                    for (int ni = 0; ni < 4; ++ni)
                        #pragma unroll
                        for (int h = 0; h < 2; ++h) {
                            const int gj = cbase + ni * 8 + h;
                            atomicAdd(&g_sumexp[gj], ce[ni][h]);
                            atomicAdd(&g_possum[gj], cp[ni][h]);
                            atomicAdd(&g_npos[gj],  cn[ni][h]);
                        }
                }
            } else {
                // diagonal tile: row-side only, exclude self
                const int j0 = bj * 128;
                #pragma unroll
                for (int ni = 0; ni < 4; ++ni) {
                    const int gj0 = j0 + wn * 32 + ni * 8 + 2 * (lane & 3);
                    const int gj1 = gj0 + 1;
                    const int lj0 = lj[ni][0], lj1 = lj[ni][1];
                    #pragma unroll
                    for (int mi = 0; mi < 4; ++mi) {
                        const int gi0 = i0 + wm * 64 + mi * 16 + (lane >> 2);
                        const int gi1 = gi0 + 8;
                        const float* d = acc[mi][ni];
                        if (gi0 != gj0) {
                            se[mi * 2] += ex2f(d[0] * TEN_LOG2E);
                            if (lj0 == labi[mi * 2]) { ps[mi * 2] += d[0]; np[mi * 2] += 1.f; }
                        }
                        if (gi0 != gj1) {
                            se[mi * 2] += ex2f(d[1] * TEN_LOG2E);
                            if (lj1 == labi[mi * 2]) { ps[mi * 2] += d[1]; np[mi * 2] += 1.f; }
                        }
                        if (gi1 != gj0) {
                            se[mi * 2 + 1] += ex2f(d[2] * TEN_LOG2E);
                            if (lj0 == labi[mi * 2 + 1]) { ps[mi * 2 + 1] += d[2]; np[mi * 2 + 1] += 1.f; }
                        }
                        if (gi1 != gj1) {
                            se[mi * 2 + 1] += ex2f(d[3] * TEN_LOG2E);
                            if (lj1 == labi[mi * 2 + 1]) { ps[mi * 2 + 1] += d[3]; np[mi * 2 + 1] += 1.f; }
                        }
                    }
                }
            }
        }

        // flush this segment's row accumulators (quad reduce + atomics)
        #pragma unroll
        for (int x = 0; x < 8; ++x) {
            float s = se[x], p = ps[x], n = np[x];
            s += __shfl_xor_sync(0xffffffffu, s, 1);
            s += __shfl_xor_sync(0xffffffffu, s, 2);
            p += __shfl_xor_sync(0xffffffffu, p, 1);
            p += __shfl_xor_sync(0xffffffffu, p, 2);
            n += __shfl_xor_sync(0xffffffffu, n, 1);
            n += __shfl_xor_sync(0xffffffffu, n, 2);
            if ((lane & 3) == 0) {
                const int gi = i0 + wm * 64 + (x >> 1) * 16 + (x & 1) * 8 + (lane >> 2);
                atomicAdd(&g_sumexp[gi], s);
                atomicAdd(&g_possum[gi], p);
                atomicAdd(&g_npos[gi],  n);
            }
        }
        u = wend;
    }
}

// ---------------------------------------------------------------------------
// Kernel 3: loss_i = npos_i*log(sumexp_i) - 10*possum_i; out = sum/N (atomic)
// ---------------------------------------------------------------------------
__global__ void finalize_kernel(float* __restrict__ out) {
    __shared__ float red[8];
    const int i = blockIdx.x * 256 + threadIdx.x;
    const int lane = threadIdx.x & 31, w = threadIdx.x >> 5;
    float v = g_npos[i] * logf(g_sumexp[i]) - 10.0f * g_possum[i];
    #pragma unroll
    for (int off = 16; off; off >>= 1) v += __shfl_xor_sync(0xffffffffu, v, off);
    if (lane == 0) red[w] = v;
    __syncthreads();
    if (threadIdx.x < 8) {
        float s = red[threadIdx.x];
        #pragma unroll
        for (int off = 4; off; off >>= 1) s += __shfl_xor_sync(0xffu, s, off);
        if (threadIdx.x == 0) atomicAdd(out, s / (float)NROW);
    }
}

extern "C" void kernel_launch(void* const* d_in, const int* in_sizes, int n_in,
                              void* d_out, int out_size) {
    const float* emb = (const float*)d_in[0];
    const int* lab   = (const int*)d_in[1];    // dtype sniffed on device
    float* out       = (float*)d_out;

    int nsm = 148;
    cudaDeviceGetAttribute(&nsm, cudaDevAttrMultiProcessorCount, 0);

    const int smem_bytes = 1024 + 3 * 32768 + 2048;  // 101376
    cudaFuncSetAttribute(sim_kernel, cudaFuncAttributeMaxDynamicSharedMemorySize,
                         smem_bytes);

    labels_kernel<<<8, 256>>>(lab, out);
    prep_kernel<<<NROW / 8, 256>>>(emb);
    sim_kernel<<<nsm, 256, smem_bytes>>>();
    finalize_kernel<<<32, 256>>>(out);
}